// round 9
// baseline (speedup 1.0000x reference)
#include <cuda_runtime.h>
#include <math.h>
#include <stdint.h>

#define NG 50000
#define ND 25000
#define CH 128
#define HC 512   // H*C = 4*128

// ---------------- scratch (device globals: no allocation allowed) ----------
__device__ float g_hg[(size_t)NG * CH];     // encoded gene
__device__ float g_hd[(size_t)ND * CH];     // encoded dis
__device__ float g_gene1[(size_t)NG * CH];  // gene after GAT1
__device__ float g_agg[(size_t)NG * CH];    // GAT aggregation buffer
__device__ float g_xs[(size_t)NG * HC];     // xs = x_src @ Ws (reused both GATs)
__device__ float g_ls[NG * 4];
__device__ float g_ld[NG * 4];
__device__ float g_m[NG * 4];
__device__ float g_den[NG * 4];
__device__ float g_wld[CH * 4];             // Wd @ a_d  (per head), layout [k][h]
__device__ float g_stats[4 * CH];           // sumG, sqG, sumD, sqD
__device__ float g_bnp[4 * CH];             // scaleG, shiftG, scaleD, shiftD

// ---------------- helpers --------------------------------------------------
__device__ __forceinline__ void atomicMaxF(float* addr, float v) {
    if (v >= 0.0f) atomicMax((int*)addr, __float_as_int(v));
    else           atomicMin((unsigned int*)addr, __float_as_uint(v));
}

__device__ __forceinline__ float lrelu02(float x) {
    return x > 0.0f ? x : 0.2f * x;
}

__device__ __forceinline__ float tf32_rna(float v) {
    uint32_t r;
    asm("cvt.rna.tf32.f32 %0, %1;" : "=r"(r) : "f"(v));
    return __uint_as_float(r);
}

#define MMA_TF32(c, a, bv0, bv1) \
    asm volatile("mma.sync.aligned.m16n8k8.row.col.f32.tf32.tf32.f32 " \
        "{%0,%1,%2,%3}, {%4,%5,%6,%7}, {%8,%9}, {%0,%1,%2,%3};" \
        : "+f"((c)[0]), "+f"((c)[1]), "+f"((c)[2]), "+f"((c)[3]) \
        : "r"((a)[0]), "r"((a)[1]), "r"((a)[2]), "r"((a)[3]), \
          "r"(bv0), "r"(bv1))

// ---------------- generic fill ---------------------------------------------
__global__ void fill_kernel(float* __restrict__ p, float v, int n) {
    int i = blockIdx.x * blockDim.x + threadIdx.x;
    if (i < n) p[i] = v;
}

// ---------------- mma.sync TF32 split GEMM ---------------------------------
// C[M,N] = A[M,K] @ B[K,N] (+bias,relu). CTA tile 128x128, K chunks of 32,
// 3xTF32 split (AhBh + AlBh + AhBl), fragment-major SMEM, double-buffered.
//
// Stage layout (65536 B per stage):
//   +0      : A hi  fragments (4 k8-steps x 8 m16-tiles x 32 lanes x 16B)
//   +16384  : A lo
//   +32768  : B hi  fragments (4 k8-steps x 16 n8-tiles x 32 lanes x 8B)
//   +49152  : B lo
#define GEMM_SMEM (2 * 65536)

__global__ void __launch_bounds__(256, 1)
sgemm_tc_kernel(const float* __restrict__ A, const float* __restrict__ B,
                const float* __restrict__ bias, float* __restrict__ C,
                int M, int N, int K, int doReluBias)
{
    extern __shared__ char smem[];
    const int tid = threadIdx.x;
    const int wid = tid >> 5;
    const int lane = tid & 31;
    const int wm = wid & 3;        // warp row  (4)  -> 32 rows each
    const int wn = wid >> 2;       // warp col  (2)  -> 64 cols each
    const int row0 = blockIdx.y * 128;
    const int col0 = blockIdx.x * 128;

    float acc[2][8][4];
#pragma unroll
    for (int mt = 0; mt < 2; mt++)
#pragma unroll
        for (int nt = 0; nt < 8; nt++)
#pragma unroll
            for (int j = 0; j < 4; j++) acc[mt][nt][j] = 0.0f;

    const int nchunks = K >> 5;

    auto ldgA = [&](int k0, float4* aP) {
#pragma unroll
        for (int i = 0; i < 4; i++) {
            int idx = tid + i * 256;
            int row = idx >> 3, t = idx & 7;
            int gr = row0 + row;
            aP[i] = (gr < M) ? *(const float4*)&A[(size_t)gr * K + k0 + t * 4]
                             : make_float4(0.f, 0.f, 0.f, 0.f);
        }
    };
    auto ldgB = [&](int k0, float4* bP) {
#pragma unroll
        for (int i = 0; i < 4; i++) {
            int idx = tid + i * 256;
            int k = idx >> 5, t = idx & 31;
            bP[i] = *(const float4*)&B[(size_t)(k0 + k) * N + col0 + t * 4];
        }
    };
    auto stsChunk = [&](const float4* aP, const float4* bP, uint32_t stage) {
        char* st = smem + stage;
        // A: element (row, k = t*4+e). Fragment coords:
        //   s=k>>3, mt=row>>4, r=row&15, j=(k&4?2:0)+(r>=8), l=(r&7)*4+(k&3)
#pragma unroll
        for (int i = 0; i < 4; i++) {
            int idx = tid + i * 256;
            int row = idx >> 3, t = idx & 7;
            int s_ = t >> 1;
            int mt = row >> 4, r = row & 15;
            int j = (t & 1) * 2 + (r >= 8 ? 1 : 0);
            uint32_t off = (uint32_t)(((s_ * 8 + mt) * 32 + (r & 7) * 4) * 16 + j * 4);
            float v[4] = {aP[i].x, aP[i].y, aP[i].z, aP[i].w};
#pragma unroll
            for (int e = 0; e < 4; e++) {
                float hi = tf32_rna(v[e]);
                *(float*)(st + off + e * 16)         = hi;
                *(float*)(st + 16384 + off + e * 16) = tf32_rna(v[e] - hi);
            }
        }
        // B: element (k, col = t*4+e). Fragment coords:
        //   s=k>>3, kk=k&7, nt=col>>3, c8=col&7, j=(kk>=4), l=c8*4+(kk&3)
#pragma unroll
        for (int i = 0; i < 4; i++) {
            int idx = tid + i * 256;
            int k = idx >> 5, t = idx & 31;
            int s_ = k >> 3, kk = k & 7;
            int j = (kk >= 4) ? 1 : 0;
            int nt = t >> 1;
            uint32_t off = (uint32_t)(32768 + (s_ * 16 + nt) * 256
                                      + (16 * (t & 1) + (kk & 3)) * 8 + j * 4);
            float v[4] = {bP[i].x, bP[i].y, bP[i].z, bP[i].w};
#pragma unroll
            for (int e = 0; e < 4; e++) {
                float hi = tf32_rna(v[e]);
                *(float*)(st + off + e * 32)         = hi;
                *(float*)(st + 16384 + off + e * 32) = tf32_rna(v[e] - hi);
            }
        }
    };
    auto compute = [&](uint32_t stage) {
        char* st = smem + stage;
#pragma unroll
        for (int s = 0; s < 4; s++) {
            uint32_t ah[2][4], al[2][4];
#pragma unroll
            for (int mt = 0; mt < 2; mt++) {
                uint32_t aoff = (uint32_t)(((s * 8 + wm * 2 + mt) * 32 + lane) * 16);
                uint4 h = *(const uint4*)(st + aoff);
                uint4 l = *(const uint4*)(st + 16384 + aoff);
                ah[mt][0] = h.x; ah[mt][1] = h.y; ah[mt][2] = h.z; ah[mt][3] = h.w;
                al[mt][0] = l.x; al[mt][1] = l.y; al[mt][2] = l.z; al[mt][3] = l.w;
            }
#pragma unroll
            for (int nt = 0; nt < 8; nt++) {
                uint32_t boff = (uint32_t)(32768 + ((s * 16 + wn * 8 + nt) * 32 + lane) * 8);
                uint2 bh = *(const uint2*)(st + boff);
                uint2 bl = *(const uint2*)(st + 16384 + boff);
#pragma unroll
                for (int mt = 0; mt < 2; mt++) {
                    MMA_TF32(acc[mt][nt], ah[mt], bh.x, bh.y);
                    MMA_TF32(acc[mt][nt], al[mt], bh.x, bh.y);
                    MMA_TF32(acc[mt][nt], ah[mt], bl.x, bl.y);
                }
            }
        }
    };

    float4 aP[4], bP[4];
    ldgA(0, aP);
    ldgB(0, bP);
    stsChunk(aP, bP, 0);
    __syncthreads();

    for (int c = 0; c < nchunks; c++) {
        uint32_t stage = (uint32_t)(c & 1) * 65536u;
        bool more = (c + 1 < nchunks);
        if (more) { ldgA((c + 1) << 5, aP); ldgB((c + 1) << 5, bP); }
        compute(stage);
        if (more) stsChunk(aP, bP, stage ^ 65536u);
        __syncthreads();
    }

    // ---- epilogue: fragment -> global, fused bias/relu ----
#pragma unroll
    for (int mt = 0; mt < 2; mt++) {
        int row  = row0 + wm * 32 + mt * 16 + (lane >> 2);
        int row2 = row + 8;
#pragma unroll
        for (int nt = 0; nt < 8; nt++) {
            int col = col0 + wn * 64 + nt * 8 + (lane & 3) * 2;
            float2 v0 = make_float2(acc[mt][nt][0], acc[mt][nt][1]);
            float2 v1 = make_float2(acc[mt][nt][2], acc[mt][nt][3]);
            if (doReluBias) {
                float b0 = bias[col], b1v = bias[col + 1];
                v0.x = fmaxf(v0.x + b0, 0.f);  v0.y = fmaxf(v0.y + b1v, 0.f);
                v1.x = fmaxf(v1.x + b0, 0.f);  v1.y = fmaxf(v1.y + b1v, 0.f);
            }
            if (row  < M) *(float2*)&C[(size_t)row  * N + col] = v0;
            if (row2 < M) *(float2*)&C[(size_t)row2 * N + col] = v1;
        }
    }
}

// ---------------- BN: column stats (sum, sumsq) ----------------------------
__global__ void colstats_kernel(const float* __restrict__ X, int rows,
                                float* __restrict__ sum, float* __restrict__ sq)
{
    int c = threadIdx.x;               // 128 threads
    int r0 = blockIdx.x * 128;
    int r1 = min(r0 + 128, rows);
    float s = 0.f, q = 0.f;
    for (int r = r0; r < r1; r++) {
        float v = X[(size_t)r * CH + c];
        s += v;
        q += v * v;
    }
    atomicAdd(&sum[c], s);
    atomicAdd(&sq[c], q);
}

__global__ void bn_finalize_kernel(const float* __restrict__ gg, const float* __restrict__ betag,
                                   const float* __restrict__ gd, const float* __restrict__ betad)
{
    int t = threadIdx.x;  // 256
    if (t < 128) {
        float mu  = g_stats[t] / (float)NG;
        float var = fmaxf(g_stats[128 + t] / (float)NG - mu * mu, 0.f);
        float sc  = gg[t] * rsqrtf(var + 1e-5f);
        g_bnp[t]       = sc;
        g_bnp[128 + t] = betag[t] - mu * sc;
    } else {
        int c = t - 128;
        float mu  = g_stats[256 + c] / (float)ND;
        float var = fmaxf(g_stats[384 + c] / (float)ND - mu * mu, 0.f);
        float sc  = gd[c] * rsqrtf(var + 1e-5f);
        g_bnp[256 + c] = sc;
        g_bnp[384 + c] = betad[c] - mu * sc;
    }
}

__global__ void bn_apply_kernel(float* __restrict__ X, int n, int off) {
    int i = blockIdx.x * blockDim.x + threadIdx.x;
    if (i < n) {
        int c = i & 127;
        X[i] = X[i] * g_bnp[off + c] + g_bnp[off + 128 + c];
    }
}

// ---------------- ls[n,h] = sum_c xs[n, h*128+c] * a_s[h,c] ----------------
__global__ void ls_kernel(const float* __restrict__ a_s, int n) {
    int w = (blockIdx.x * blockDim.x + threadIdx.x) >> 5;
    int lane = threadIdx.x & 31;
    if (w >= n) return;
    const float4* xr = (const float4*)(g_xs + (size_t)w * HC);
    const float4* ar = (const float4*)a_s;
    float p0, p1, p2, p3;
    {
        float4 x = xr[lane],      a = ar[lane];
        p0 = x.x * a.x + x.y * a.y + x.z * a.z + x.w * a.w;
    }
    {
        float4 x = xr[32 + lane], a = ar[32 + lane];
        p1 = x.x * a.x + x.y * a.y + x.z * a.z + x.w * a.w;
    }
    {
        float4 x = xr[64 + lane], a = ar[64 + lane];
        p2 = x.x * a.x + x.y * a.y + x.z * a.z + x.w * a.w;
    }
    {
        float4 x = xr[96 + lane], a = ar[96 + lane];
        p3 = x.x * a.x + x.y * a.y + x.z * a.z + x.w * a.w;
    }
#pragma unroll
    for (int off = 16; off > 0; off >>= 1) {
        p0 += __shfl_xor_sync(0xffffffffu, p0, off);
        p1 += __shfl_xor_sync(0xffffffffu, p1, off);
        p2 += __shfl_xor_sync(0xffffffffu, p2, off);
        p3 += __shfl_xor_sync(0xffffffffu, p3, off);
    }
    if (lane == 0) *(float4*)&g_ls[w * 4] = make_float4(p0, p1, p2, p3);
}

// ---------------- wld[k,h] = sum_c Wd[k, h*128+c] * a_d[h,c] ---------------
__global__ void wld_kernel(const float* __restrict__ Wd, const float* __restrict__ a_d) {
    int w = (blockIdx.x * blockDim.x + threadIdx.x) >> 5;
    int lane = threadIdx.x & 31;
    if (w >= 512) return;
    int k = w >> 2, h = w & 3;
    const float4* wr = (const float4*)(Wd + (size_t)k * HC + h * 128);
    const float4* ar = (const float4*)(a_d + h * 128);
    float4 x = wr[lane], a = ar[lane];
    float p = x.x * a.x + x.y * a.y + x.z * a.z + x.w * a.w;
#pragma unroll
    for (int off = 16; off > 0; off >>= 1) p += __shfl_xor_sync(0xffffffffu, p, off);
    if (lane == 0) g_wld[k * 4 + h] = p;
}

// ---------------- ld[n,h] = sum_k X[n,k] * wld[k,h] ------------------------
__global__ void ld_kernel(const float* __restrict__ X, int n) {
    int w = (blockIdx.x * blockDim.x + threadIdx.x) >> 5;
    int lane = threadIdx.x & 31;
    if (w >= n) return;
    const float4* xr = (const float4*)(X + (size_t)w * CH);
    float4 x = xr[lane];
    const float4* wl = (const float4*)g_wld;   // wl[k] = 4 heads of k
    float4 p = make_float4(0.f, 0.f, 0.f, 0.f);
    float4 wv;
    wv = wl[lane * 4 + 0]; p.x += x.x * wv.x; p.y += x.x * wv.y; p.z += x.x * wv.z; p.w += x.x * wv.w;
    wv = wl[lane * 4 + 1]; p.x += x.y * wv.x; p.y += x.y * wv.y; p.z += x.y * wv.z; p.w += x.y * wv.w;
    wv = wl[lane * 4 + 2]; p.x += x.z * wv.x; p.y += x.z * wv.y; p.z += x.z * wv.z; p.w += x.z * wv.w;
    wv = wl[lane * 4 + 3]; p.x += x.w * wv.x; p.y += x.w * wv.y; p.z += x.w * wv.z; p.w += x.w * wv.w;
#pragma unroll
    for (int off = 16; off > 0; off >>= 1) {
        p.x += __shfl_xor_sync(0xffffffffu, p.x, off);
        p.y += __shfl_xor_sync(0xffffffffu, p.y, off);
        p.z += __shfl_xor_sync(0xffffffffu, p.z, off);
        p.w += __shfl_xor_sync(0xffffffffu, p.w, off);
    }
    if (lane == 0) *(float4*)&g_ld[w * 4] = p;
}

// ---------------- edge pass A: segment max ---------------------------------
__global__ void edge_max_kernel(const int* __restrict__ src, const int* __restrict__ dst,
                                int nE, int nLoop)
{
    int e = blockIdx.x * blockDim.x + threadIdx.x;
    if (e >= nE + nLoop) return;
    int s, d;
    if (e < nE) { s = src[e]; d = dst[e]; if (s == d) return; }
    else        { s = d = e - nE; }
    float4 lsv = *(const float4*)&g_ls[s * 4];
    float4 ldv = *(const float4*)&g_ld[d * 4];
    atomicMaxF(&g_m[d * 4 + 0], lrelu02(lsv.x + ldv.x));
    atomicMaxF(&g_m[d * 4 + 1], lrelu02(lsv.y + ldv.y));
    atomicMaxF(&g_m[d * 4 + 2], lrelu02(lsv.z + ldv.z));
    atomicMaxF(&g_m[d * 4 + 3], lrelu02(lsv.w + ldv.w));
}

// ---------------- edge pass B: denominator ---------------------------------
__global__ void edge_den_kernel(const int* __restrict__ src, const int* __restrict__ dst,
                                int nE, int nLoop)
{
    int e = blockIdx.x * blockDim.x + threadIdx.x;
    if (e >= nE + nLoop) return;
    int s, d;
    if (e < nE) { s = src[e]; d = dst[e]; if (s == d) return; }
    else        { s = d = e - nE; }
    float4 lsv = *(const float4*)&g_ls[s * 4];
    float4 ldv = *(const float4*)&g_ld[d * 4];
    float4 mv  = *(const float4*)&g_m[d * 4];
    atomicAdd(&g_den[d * 4 + 0], expf(lrelu02(lsv.x + ldv.x) - mv.x));
    atomicAdd(&g_den[d * 4 + 1], expf(lrelu02(lsv.y + ldv.y) - mv.y));
    atomicAdd(&g_den[d * 4 + 2], expf(lrelu02(lsv.z + ldv.z) - mv.z));
    atomicAdd(&g_den[d * 4 + 3], expf(lrelu02(lsv.w + ldv.w) - mv.w));
}

// ---------------- edge pass C: weighted aggregation (warp per edge) --------
__global__ void edge_agg_kernel(const int* __restrict__ src, const int* __restrict__ dst,
                                int nE, int nLoop)
{
    int gw = (blockIdx.x * blockDim.x + threadIdx.x) >> 5;
    int lane = threadIdx.x & 31;
    if (gw >= nE + nLoop) return;
    int s, d;
    if (gw < nE) { s = src[gw]; d = dst[gw]; if (s == d) return; }
    else         { s = d = gw - nE; }
    float4 lsv = *(const float4*)&g_ls[s * 4];
    float4 ldv = *(const float4*)&g_ld[d * 4];
    float4 mv  = *(const float4*)&g_m[d * 4];
    float4 dv  = *(const float4*)&g_den[d * 4];
    float l;
    l = lsv.x + ldv.x; l = lrelu02(l);
    float a0 = 0.25f * expf(l - mv.x) / (dv.x > 0.f ? dv.x : 1.f);
    l = lsv.y + ldv.y; l = lrelu02(l);
    float a1 = 0.25f * expf(l - mv.y) / (dv.y > 0.f ? dv.y : 1.f);
    l = lsv.z + ldv.z; l = lrelu02(l);
    float a2 = 0.25f * expf(l - mv.z) / (dv.z > 0.f ? dv.z : 1.f);
    l = lsv.w + ldv.w; l = lrelu02(l);
    float a3 = 0.25f * expf(l - mv.w) / (dv.w > 0.f ? dv.w : 1.f);

    const float4* xr = (const float4*)(g_xs + (size_t)s * HC);
    float4 v, acc;
    v = xr[lane];
    acc.x = a0 * v.x; acc.y = a0 * v.y; acc.z = a0 * v.z; acc.w = a0 * v.w;
    v = xr[32 + lane];
    acc.x += a1 * v.x; acc.y += a1 * v.y; acc.z += a1 * v.z; acc.w += a1 * v.w;
    v = xr[64 + lane];
    acc.x += a2 * v.x; acc.y += a2 * v.y; acc.z += a2 * v.z; acc.w += a2 * v.w;
    v = xr[96 + lane];
    acc.x += a3 * v.x; acc.y += a3 * v.y; acc.z += a3 * v.z; acc.w += a3 * v.w;

    float* p = &g_agg[(size_t)d * CH + lane * 4];
    asm volatile("red.global.add.v4.f32 [%0], {%1,%2,%3,%4};"
                 :: "l"(p), "f"(acc.x), "f"(acc.y), "f"(acc.z), "f"(acc.w)
                 : "memory");
}

// ---------------- combine: out = base + agg + bias -------------------------
__global__ void combine_kernel(const float* __restrict__ base, const float* __restrict__ bias,
                               float* __restrict__ out, int n)
{
    int i = blockIdx.x * blockDim.x + threadIdx.x;
    if (i < n) {
        int c = i & 127;
        out[i] = base[i] + g_agg[i] + bias[c];
    }
}

__global__ void copy_kernel(const float* __restrict__ srcp, float* __restrict__ dstp, int n) {
    int i = blockIdx.x * blockDim.x + threadIdx.x;
    if (i < n) dstp[i] = srcp[i];
}

// ---------------- host orchestration ---------------------------------------
extern "C" void kernel_launch(void* const* d_in, const int* in_sizes, int n_in,
                              void* d_out, int out_size)
{
    const float* x_gene = (const float*)d_in[0];
    const float* x_dis  = (const float*)d_in[1];
    const int* e1_src   = (const int*)d_in[2];
    const int* e1_dst   = (const int*)d_in[3];
    const int* e2_src   = (const int*)d_in[4];
    const int* e2_dst   = (const int*)d_in[5];
    const float* Wg     = (const float*)d_in[6];
    const float* bg     = (const float*)d_in[7];
    const float* gg     = (const float*)d_in[8];
    const float* betag  = (const float*)d_in[9];
    const float* Wd     = (const float*)d_in[10];
    const float* bd     = (const float*)d_in[11];
    const float* gd     = (const float*)d_in[12];
    const float* betad  = (const float*)d_in[13];
    const float* W1s    = (const float*)d_in[14];
    const float* W1d    = (const float*)d_in[15];
    const float* a1s    = (const float*)d_in[16];
    const float* a1d    = (const float*)d_in[17];
    const float* b1     = (const float*)d_in[18];
    const float* W2s    = (const float*)d_in[19];
    const float* W2d    = (const float*)d_in[20];
    const float* a2s    = (const float*)d_in[21];
    const float* a2d    = (const float*)d_in[22];
    const float* b2     = (const float*)d_in[23];

    const int E1 = in_sizes[2];
    const int E2 = in_sizes[4];
    const int Fg = in_sizes[0] / NG;   // 512
    const int Fd = in_sizes[1] / ND;   // 256

    float *hg, *hd, *gene1, *xs, *agg, *mbuf, *den, *stats;
    cudaGetSymbolAddress((void**)&hg, g_hg);
    cudaGetSymbolAddress((void**)&hd, g_hd);
    cudaGetSymbolAddress((void**)&gene1, g_gene1);
    cudaGetSymbolAddress((void**)&xs, g_xs);
    cudaGetSymbolAddress((void**)&agg, g_agg);
    cudaGetSymbolAddress((void**)&mbuf, g_m);
    cudaGetSymbolAddress((void**)&den, g_den);
    cudaGetSymbolAddress((void**)&stats, g_stats);

    cudaFuncSetAttribute(sgemm_tc_kernel,
                         cudaFuncAttributeMaxDynamicSharedMemorySize, GEMM_SMEM);

    float* out_gene = (float*)d_out;
    float* out_dis  = (float*)d_out + (size_t)NG * CH;

    const int T = 256;
    auto blocks = [](int n, int t) { return (n + t - 1) / t; };

    // -------- encoders --------
    fill_kernel<<<2, T>>>(stats, 0.f, 4 * CH);
    sgemm_tc_kernel<<<dim3(1, blocks(NG, 128)), 256, GEMM_SMEM>>>(x_gene, Wg, bg, hg, NG, CH, Fg, 1);
    sgemm_tc_kernel<<<dim3(1, blocks(ND, 128)), 256, GEMM_SMEM>>>(x_dis,  Wd, bd, hd, ND, CH, Fd, 1);
    colstats_kernel<<<blocks(NG, 128), 128>>>(hg, NG, stats, stats + 128);
    colstats_kernel<<<blocks(ND, 128), 128>>>(hd, ND, stats + 256, stats + 384);
    bn_finalize_kernel<<<1, 256>>>(gg, betag, gd, betad);
    bn_apply_kernel<<<blocks(NG * CH, T), T>>>(hg, NG * CH, 0);
    bn_apply_kernel<<<blocks(ND * CH, T), T>>>(hd, ND * CH, 256);

    // -------- GAT 1: dis -> gene --------
    fill_kernel<<<blocks(NG * 4, T), T>>>(mbuf, -INFINITY, NG * 4);
    fill_kernel<<<blocks(NG * 4, T), T>>>(den, 0.f, NG * 4);
    fill_kernel<<<blocks(NG * CH, T), T>>>(agg, 0.f, NG * CH);
    sgemm_tc_kernel<<<dim3(4, blocks(ND, 128)), 256, GEMM_SMEM>>>(hd, W1s, nullptr, xs, ND, HC, CH, 0);
    ls_kernel<<<blocks(ND * 32, T), T>>>(a1s, ND);
    wld_kernel<<<blocks(512 * 32, T), T>>>(W1d, a1d);
    ld_kernel<<<blocks(NG * 32, T), T>>>(hg, NG);
    {
        int nT = E1 + ND;
        edge_max_kernel<<<blocks(nT, T), T>>>(e1_src, e1_dst, E1, ND);
        edge_den_kernel<<<blocks(nT, T), T>>>(e1_src, e1_dst, E1, ND);
        edge_agg_kernel<<<blocks(nT * 32, T), T>>>(e1_src, e1_dst, E1, ND);
    }
    combine_kernel<<<blocks(NG * CH, T), T>>>(hg, b1, gene1, NG * CH);

    // -------- GAT 2: gene -> gene --------
    fill_kernel<<<blocks(NG * 4, T), T>>>(mbuf, -INFINITY, NG * 4);
    fill_kernel<<<blocks(NG * 4, T), T>>>(den, 0.f, NG * 4);
    fill_kernel<<<blocks(NG * CH, T), T>>>(agg, 0.f, NG * CH);
    sgemm_tc_kernel<<<dim3(4, blocks(NG, 128)), 256, GEMM_SMEM>>>(gene1, W2s, nullptr, xs, NG, HC, CH, 0);
    ls_kernel<<<blocks(NG * 32, T), T>>>(a2s, NG);
    wld_kernel<<<blocks(512 * 32, T), T>>>(W2d, a2d);
    ld_kernel<<<blocks(NG * 32, T), T>>>(gene1, NG);
    {
        int nT = E2 + NG;
        edge_max_kernel<<<blocks(nT, T), T>>>(e2_src, e2_dst, E2, NG);
        edge_den_kernel<<<blocks(nT, T), T>>>(e2_src, e2_dst, E2, NG);
        edge_agg_kernel<<<blocks(nT * 32, T), T>>>(e2_src, e2_dst, E2, NG);
    }

    // -------- outputs: [gene | dis] --------
    combine_kernel<<<blocks(NG * CH, T), T>>>(gene1, b2, out_gene, NG * CH);
    copy_kernel<<<blocks(ND * CH, T), T>>>(hd, out_dis, ND * CH);
}

// round 12
// speedup vs baseline: 2.3769x; 2.3769x over previous
#include <cuda_runtime.h>
#include <math.h>
#include <stdint.h>

#define NG 50000
#define ND 25000
#define CH 128
#define HC 512   // H*C = 4*128

typedef unsigned long long ull;

// ---------------- scratch (device globals: no allocation allowed) ----------
__device__ float g_hg[(size_t)NG * CH];     // encoded gene (pre-BN)
__device__ float g_hd[(size_t)ND * CH];     // encoded dis  (pre-BN)
__device__ float g_gene1[(size_t)NG * CH];  // gene after GAT1
__device__ float g_agg[(size_t)NG * CH];    // GAT aggregation buffer
__device__ float g_xs[(size_t)NG * HC];     // xs = x_src @ Ws (reused both GATs)
__device__ float g_ls[NG * 4];
__device__ float g_ld[NG * 4];
__device__ float g_m[NG * 4];
__device__ float g_den[NG * 4];
__device__ float g_wld[CH * 4];             // (scaled) Wd @ a_d, layout [k][h]
__device__ float g_wldraw[CH * 4];          // unscaled Wd @ a_d
__device__ float g_wldc[4];                 // shift term for ld
__device__ float g_stats[4 * CH];           // sumG, sqG, sumD, sqD
__device__ float g_bnp[4 * CH];             // scaleG, shiftG, scaleD, shiftD
__device__ float g_w1sf[CH * HC];           // diag(scD) @ W1s
__device__ float g_shW[HC];                 // shD @ W1s

// ---------------- helpers --------------------------------------------------
__device__ __forceinline__ void atomicMaxF(float* addr, float v) {
    if (v >= 0.0f) atomicMax((int*)addr, __float_as_int(v));
    else           atomicMin((unsigned int*)addr, __float_as_uint(v));
}

__device__ __forceinline__ float lrelu02(float x) {
    return x > 0.0f ? x : 0.2f * x;
}

__device__ __forceinline__ ull pk2(float x, float y) {
    ull r;
    asm("mov.b64 %0, {%1, %2};" : "=l"(r) : "f"(x), "f"(y));
    return r;
}

#define FMA2(c, a, b) \
    asm("fma.rn.f32x2 %0, %1, %2, %0;" : "+l"(c) : "l"(a), "l"(b))

// ---------------- generic fill ---------------------------------------------
__global__ void fill_kernel(float* __restrict__ p, float v, int n) {
    int i = blockIdx.x * blockDim.x + threadIdx.x;
    if (i < n) p[i] = v;
}

// ---------------- SGEMM (FFMA2): C[M,N] = A[M,K] @ B[K,N] ------------------
// BM=BN=128, BK=16, 256 threads, 8x8 microtile, packed-f32x2 inner loop.
// mode: 0 = none, 1 = bias+relu, 2 = bias only
__global__ __launch_bounds__(256, 2)
void sgemm_kernel(const float* __restrict__ A, const float* __restrict__ B,
                  const float* __restrict__ bias, float* __restrict__ C,
                  int M, int N, int K, int mode)
{
    __shared__ float As[16][128];
    __shared__ float Bs[16][128];

    const int tid = threadIdx.x;
    const int tx = tid & 15;     // column group (8 cols each)
    const int ty = tid >> 4;     // row group (8 rows each)
    const int row0 = blockIdx.y * 128;
    const int col0 = blockIdx.x * 128;

    // acc[j][i2]: column j (8), row-pair i2 (4) -> rows (2*i2, 2*i2+1)
    ull acc[8][4];
#pragma unroll
    for (int j = 0; j < 8; j++)
#pragma unroll
        for (int i2 = 0; i2 < 4; i2++) acc[j][i2] = 0ull;

    const int aRow = tid >> 2;          // 0..63
    const int aCol = (tid & 3) * 4;     // 0,4,8,12
    const int bRow = tid >> 5;          // 0..7
    const int bCol = (tid & 31) * 4;    // 0..124

    for (int k0 = 0; k0 < K; k0 += 16) {
        // A tile (transposed into As[k][m])
#pragma unroll
        for (int half = 0; half < 2; half++) {
            int r = aRow + half * 64;
            int gr = row0 + r;
            float4 v = make_float4(0.f, 0.f, 0.f, 0.f);
            if (gr < M) v = *(const float4*)&A[(size_t)gr * K + k0 + aCol];
            As[aCol + 0][r] = v.x;
            As[aCol + 1][r] = v.y;
            As[aCol + 2][r] = v.z;
            As[aCol + 3][r] = v.w;
        }
        // B tile
#pragma unroll
        for (int half = 0; half < 2; half++) {
            int r = bRow + half * 8;
            float4 v = *(const float4*)&B[(size_t)(k0 + r) * N + col0 + bCol];
            *(float4*)&Bs[r][bCol] = v;
        }
        __syncthreads();

#pragma unroll
        for (int k = 0; k < 16; k++) {
            const float2* ap = (const float2*)&As[k][ty * 8];
            ull a2[4];
            a2[0] = pk2(ap[0].x, ap[0].y);
            a2[1] = pk2(ap[1].x, ap[1].y);
            a2[2] = pk2(ap[2].x, ap[2].y);
            a2[3] = pk2(ap[3].x, ap[3].y);
            float4 bq0 = *(const float4*)&Bs[k][tx * 8];
            float4 bq1 = *(const float4*)&Bs[k][tx * 8 + 4];
            float bj[8] = {bq0.x, bq0.y, bq0.z, bq0.w,
                           bq1.x, bq1.y, bq1.z, bq1.w};
#pragma unroll
            for (int j = 0; j < 8; j++) {
                ull bb;
                asm("mov.b64 %0, {%1, %1};" : "=l"(bb) : "f"(bj[j]));
                FMA2(acc[j][0], a2[0], bb);
                FMA2(acc[j][1], a2[1], bb);
                FMA2(acc[j][2], a2[2], bb);
                FMA2(acc[j][3], a2[3], bb);
            }
        }
        __syncthreads();
    }

    // ---- epilogue ----
#pragma unroll
    for (int r = 0; r < 8; r++) {
        int gr = row0 + ty * 8 + r;
        if (gr >= M) continue;
        int i2 = r >> 1;
        int sel = r & 1;
        float vals[8];
#pragma unroll
        for (int j = 0; j < 8; j++) {
            float lo, hi;
            asm("mov.b64 {%0, %1}, %2;" : "=f"(lo), "=f"(hi) : "l"(acc[j][i2]));
            vals[j] = sel ? hi : lo;
        }
        int gc = col0 + tx * 8;
        if (mode == 1) {
#pragma unroll
            for (int j = 0; j < 8; j++) vals[j] = fmaxf(vals[j] + bias[gc + j], 0.f);
        } else if (mode == 2) {
#pragma unroll
            for (int j = 0; j < 8; j++) vals[j] = vals[j] + bias[gc + j];
        }
        float4 v0 = make_float4(vals[0], vals[1], vals[2], vals[3]);
        float4 v1 = make_float4(vals[4], vals[5], vals[6], vals[7]);
        *(float4*)&C[(size_t)gr * N + gc]     = v0;
        *(float4*)&C[(size_t)gr * N + gc + 4] = v1;
    }
}

// ---------------- BN: column stats (sum, sumsq) ----------------------------
__global__ void colstats_kernel(const float* __restrict__ X, int rows,
                                float* __restrict__ sum, float* __restrict__ sq)
{
    int c = threadIdx.x;               // 128 threads
    int r0 = blockIdx.x * 128;
    int r1 = min(r0 + 128, rows);
    float s = 0.f, q = 0.f;
    for (int r = r0; r < r1; r++) {
        float v = X[(size_t)r * CH + c];
        s += v;
        q += v * v;
    }
    atomicAdd(&sum[c], s);
    atomicAdd(&sq[c], q);
}

__global__ void bn_finalize_kernel(const float* __restrict__ gg, const float* __restrict__ betag,
                                   const float* __restrict__ gd, const float* __restrict__ betad)
{
    int t = threadIdx.x;  // 256
    if (t < 128) {
        float mu  = g_stats[t] / (float)NG;
        float var = fmaxf(g_stats[128 + t] / (float)NG - mu * mu, 0.f);
        float sc  = gg[t] * rsqrtf(var + 1e-5f);
        g_bnp[t]       = sc;
        g_bnp[128 + t] = betag[t] - mu * sc;
    } else {
        int c = t - 128;
        float mu  = g_stats[256 + c] / (float)ND;
        float var = fmaxf(g_stats[384 + c] / (float)ND - mu * mu, 0.f);
        float sc  = gd[c] * rsqrtf(var + 1e-5f);
        g_bnp[256 + c] = sc;
        g_bnp[384 + c] = betad[c] - mu * sc;
    }
}

// ---------------- fold BN into W1s: W' = diag(sc)W, shW = sh @ W ------------
// 512 threads total (one per output column j).
__global__ void scaleW_kernel(const float* __restrict__ W) {
    int j = blockIdx.x * blockDim.x + threadIdx.x;
    if (j >= HC) return;
    const float* sc = g_bnp + 256;   // disease scale
    const float* sh = g_bnp + 384;   // disease shift
    float acc = 0.f;
#pragma unroll 4
    for (int k = 0; k < CH; k++) {
        float w = W[(size_t)k * HC + j];
        g_w1sf[(size_t)k * HC + j] = w * sc[k];
        acc += sh[k] * w;
    }
    g_shW[j] = acc;
}

// ---------------- ls[n,h] = sum_c xs[n, h*128+c] * a_s[h,c] ----------------
__global__ void ls_kernel(const float* __restrict__ a_s, int n) {
    int w = (blockIdx.x * blockDim.x + threadIdx.x) >> 5;
    int lane = threadIdx.x & 31;
    if (w >= n) return;
    const float4* xr = (const float4*)(g_xs + (size_t)w * HC);
    const float4* ar = (const float4*)a_s;
    float p0, p1, p2, p3;
    {
        float4 x = xr[lane],      a = ar[lane];
        p0 = x.x * a.x + x.y * a.y + x.z * a.z + x.w * a.w;
    }
    {
        float4 x = xr[32 + lane], a = ar[32 + lane];
        p1 = x.x * a.x + x.y * a.y + x.z * a.z + x.w * a.w;
    }
    {
        float4 x = xr[64 + lane], a = ar[64 + lane];
        p2 = x.x * a.x + x.y * a.y + x.z * a.z + x.w * a.w;
    }
    {
        float4 x = xr[96 + lane], a = ar[96 + lane];
        p3 = x.x * a.x + x.y * a.y + x.z * a.z + x.w * a.w;
    }
#pragma unroll
    for (int off = 16; off > 0; off >>= 1) {
        p0 += __shfl_xor_sync(0xffffffffu, p0, off);
        p1 += __shfl_xor_sync(0xffffffffu, p1, off);
        p2 += __shfl_xor_sync(0xffffffffu, p2, off);
        p3 += __shfl_xor_sync(0xffffffffu, p3, off);
    }
    if (lane == 0) *(float4*)&g_ls[w * 4] = make_float4(p0, p1, p2, p3);
}

// ---------------- wld[k,h] = sum_c Wd[k, h*128+c] * a_d[h,c] ---------------
// useScale: multiply by gene BN scale (fold BN of x_dst into wld)
__global__ void wld_kernel(const float* __restrict__ Wd, const float* __restrict__ a_d,
                           int useScale) {
    int w = (blockIdx.x * blockDim.x + threadIdx.x) >> 5;
    int lane = threadIdx.x & 31;
    if (w >= 512) return;
    int k = w >> 2, h = w & 3;
    const float4* wr = (const float4*)(Wd + (size_t)k * HC + h * 128);
    const float4* ar = (const float4*)(a_d + h * 128);
    float4 x = wr[lane], a = ar[lane];
    float p = x.x * a.x + x.y * a.y + x.z * a.z + x.w * a.w;
#pragma unroll
    for (int off = 16; off > 0; off >>= 1) p += __shfl_xor_sync(0xffffffffu, p, off);
    if (lane == 0) {
        g_wldraw[k * 4 + h] = p;
        g_wld[k * 4 + h] = useScale ? p * g_bnp[k] : p;
    }
}

// c[h] = sum_k shG[k] * wldraw[k,h]  (one block, 128 threads)
__global__ void ldc_kernel() {
    int k = threadIdx.x;
    if (k < 4) g_wldc[k] = 0.f;
    __syncthreads();
    float sh = g_bnp[128 + k];
#pragma unroll
    for (int h = 0; h < 4; h++)
        atomicAdd(&g_wldc[h], sh * g_wldraw[k * 4 + h]);
}

// ---------------- ld[n,h] = sum_k X[n,k] * wld[k,h] + c[h] -----------------
__global__ void ld_kernel(const float* __restrict__ X, int n) {
    int w = (blockIdx.x * blockDim.x + threadIdx.x) >> 5;
    int lane = threadIdx.x & 31;
    if (w >= n) return;
    const float4* xr = (const float4*)(X + (size_t)w * CH);
    float4 x = xr[lane];
    const float4* wl = (const float4*)g_wld;   // wl[k] = 4 heads of k
    float4 p = make_float4(0.f, 0.f, 0.f, 0.f);
    float4 wv;
    wv = wl[lane * 4 + 0]; p.x += x.x * wv.x; p.y += x.x * wv.y; p.z += x.x * wv.z; p.w += x.x * wv.w;
    wv = wl[lane * 4 + 1]; p.x += x.y * wv.x; p.y += x.y * wv.y; p.z += x.y * wv.z; p.w += x.y * wv.w;
    wv = wl[lane * 4 + 2]; p.x += x.z * wv.x; p.y += x.z * wv.y; p.z += x.z * wv.z; p.w += x.z * wv.w;
    wv = wl[lane * 4 + 3]; p.x += x.w * wv.x; p.y += x.w * wv.y; p.z += x.w * wv.z; p.w += x.w * wv.w;
#pragma unroll
    for (int off = 16; off > 0; off >>= 1) {
        p.x += __shfl_xor_sync(0xffffffffu, p.x, off);
        p.y += __shfl_xor_sync(0xffffffffu, p.y, off);
        p.z += __shfl_xor_sync(0xffffffffu, p.z, off);
        p.w += __shfl_xor_sync(0xffffffffu, p.w, off);
    }
    if (lane == 0) {
        float4 c = *(const float4*)g_wldc;
        *(float4*)&g_ld[w * 4] = make_float4(p.x + c.x, p.y + c.y, p.z + c.z, p.w + c.w);
    }
}

// ---------------- edge pass A: segment max ---------------------------------
__global__ void edge_max_kernel(const int* __restrict__ src, const int* __restrict__ dst,
                                int nE, int nLoop)
{
    int e = blockIdx.x * blockDim.x + threadIdx.x;
    if (e >= nE + nLoop) return;
    int s, d;
    if (e < nE) { s = src[e]; d = dst[e]; if (s == d) return; }
    else        { s = d = e - nE; }
    float4 lsv = *(const float4*)&g_ls[s * 4];
    float4 ldv = *(const float4*)&g_ld[d * 4];
    atomicMaxF(&g_m[d * 4 + 0], lrelu02(lsv.x + ldv.x));
    atomicMaxF(&g_m[d * 4 + 1], lrelu02(lsv.y + ldv.y));
    atomicMaxF(&g_m[d * 4 + 2], lrelu02(lsv.z + ldv.z));
    atomicMaxF(&g_m[d * 4 + 3], lrelu02(lsv.w + ldv.w));
}

// ---------------- edge pass B: denominator ---------------------------------
__global__ void edge_den_kernel(const int* __restrict__ src, const int* __restrict__ dst,
                                int nE, int nLoop)
{
    int e = blockIdx.x * blockDim.x + threadIdx.x;
    if (e >= nE + nLoop) return;
    int s, d;
    if (e < nE) { s = src[e]; d = dst[e]; if (s == d) return; }
    else        { s = d = e - nE; }
    float4 lsv = *(const float4*)&g_ls[s * 4];
    float4 ldv = *(const float4*)&g_ld[d * 4];
    float4 mv  = *(const float4*)&g_m[d * 4];
    atomicAdd(&g_den[d * 4 + 0], expf(lrelu02(lsv.x + ldv.x) - mv.x));
    atomicAdd(&g_den[d * 4 + 1], expf(lrelu02(lsv.y + ldv.y) - mv.y));
    atomicAdd(&g_den[d * 4 + 2], expf(lrelu02(lsv.z + ldv.z) - mv.z));
    atomicAdd(&g_den[d * 4 + 3], expf(lrelu02(lsv.w + ldv.w) - mv.w));
}

// ---------------- edge pass C: weighted aggregation (warp per edge) --------
__global__ void edge_agg_kernel(const int* __restrict__ src, const int* __restrict__ dst,
                                int nE, int nLoop)
{
    int gw = (blockIdx.x * blockDim.x + threadIdx.x) >> 5;
    int lane = threadIdx.x & 31;
    if (gw >= nE + nLoop) return;
    int s, d;
    if (gw < nE) { s = src[gw]; d = dst[gw]; if (s == d) return; }
    else         { s = d = gw - nE; }
    float4 lsv = *(const float4*)&g_ls[s * 4];
    float4 ldv = *(const float4*)&g_ld[d * 4];
    float4 mv  = *(const float4*)&g_m[d * 4];
    float4 dv  = *(const float4*)&g_den[d * 4];
    float l;
    l = lsv.x + ldv.x; l = lrelu02(l);
    float a0 = 0.25f * expf(l - mv.x) / (dv.x > 0.f ? dv.x : 1.f);
    l = lsv.y + ldv.y; l = lrelu02(l);
    float a1 = 0.25f * expf(l - mv.y) / (dv.y > 0.f ? dv.y : 1.f);
    l = lsv.z + ldv.z; l = lrelu02(l);
    float a2 = 0.25f * expf(l - mv.z) / (dv.z > 0.f ? dv.z : 1.f);
    l = lsv.w + ldv.w; l = lrelu02(l);
    float a3 = 0.25f * expf(l - mv.w) / (dv.w > 0.f ? dv.w : 1.f);

    const float4* xr = (const float4*)(g_xs + (size_t)s * HC);
    float4 v, acc;
    v = xr[lane];
    acc.x = a0 * v.x; acc.y = a0 * v.y; acc.z = a0 * v.z; acc.w = a0 * v.w;
    v = xr[32 + lane];
    acc.x += a1 * v.x; acc.y += a1 * v.y; acc.z += a1 * v.z; acc.w += a1 * v.w;
    v = xr[64 + lane];
    acc.x += a2 * v.x; acc.y += a2 * v.y; acc.z += a2 * v.z; acc.w += a2 * v.w;
    v = xr[96 + lane];
    acc.x += a3 * v.x; acc.y += a3 * v.y; acc.z += a3 * v.z; acc.w += a3 * v.w;

    float* p = &g_agg[(size_t)d * CH + lane * 4];
    asm volatile("red.global.add.v4.f32 [%0], {%1,%2,%3,%4};"
                 :: "l"(p), "f"(acc.x), "f"(acc.y), "f"(acc.z), "f"(acc.w)
                 : "memory");
}

// ---------------- combine variants -----------------------------------------
// gene1 = BN(hg) + agg + b1  (affine folded here)
__global__ void combine_affine_kernel(const float* __restrict__ base,
                                      const float* __restrict__ bias,
                                      float* __restrict__ out, int n)
{
    int i = blockIdx.x * blockDim.x + threadIdx.x;
    if (i < n) {
        int c = i & 127;
        out[i] = base[i] * g_bnp[c] + g_bnp[128 + c] + g_agg[i] + bias[c];
    }
}

__global__ void combine_kernel(const float* __restrict__ base, const float* __restrict__ bias,
                               float* __restrict__ out, int n)
{
    int i = blockIdx.x * blockDim.x + threadIdx.x;
    if (i < n) {
        int c = i & 127;
        out[i] = base[i] + g_agg[i] + bias[c];
    }
}

// out_dis = BN(hd)
__global__ void copy_affine_kernel(const float* __restrict__ srcp,
                                   float* __restrict__ dstp, int n) {
    int i = blockIdx.x * blockDim.x + threadIdx.x;
    if (i < n) {
        int c = i & 127;
        dstp[i] = srcp[i] * g_bnp[256 + c] + g_bnp[384 + c];
    }
}

// ---------------- host orchestration ---------------------------------------
extern "C" void kernel_launch(void* const* d_in, const int* in_sizes, int n_in,
                              void* d_out, int out_size)
{
    const float* x_gene = (const float*)d_in[0];
    const float* x_dis  = (const float*)d_in[1];
    const int* e1_src   = (const int*)d_in[2];
    const int* e1_dst   = (const int*)d_in[3];
    const int* e2_src   = (const int*)d_in[4];
    const int* e2_dst   = (const int*)d_in[5];
    const float* Wg     = (const float*)d_in[6];
    const float* bg     = (const float*)d_in[7];
    const float* gg     = (const float*)d_in[8];
    const float* betag  = (const float*)d_in[9];
    const float* Wd     = (const float*)d_in[10];
    const float* bd     = (const float*)d_in[11];
    const float* gd     = (const float*)d_in[12];
    const float* betad  = (const float*)d_in[13];
    const float* W1s    = (const float*)d_in[14];
    const float* W1d    = (const float*)d_in[15];
    const float* a1s    = (const float*)d_in[16];
    const float* a1d    = (const float*)d_in[17];
    const float* b1     = (const float*)d_in[18];
    const float* W2s    = (const float*)d_in[19];
    const float* W2d    = (const float*)d_in[20];
    const float* a2s    = (const float*)d_in[21];
    const float* a2d    = (const float*)d_in[22];
    const float* b2     = (const float*)d_in[23];

    const int E1 = in_sizes[2];
    const int E2 = in_sizes[4];
    const int Fg = in_sizes[0] / NG;   // 512
    const int Fd = in_sizes[1] / ND;   // 256

    float *hg, *hd, *gene1, *xs, *agg, *mbuf, *den, *stats, *w1sf, *shW, *wldc;
    cudaGetSymbolAddress((void**)&hg, g_hg);
    cudaGetSymbolAddress((void**)&hd, g_hd);
    cudaGetSymbolAddress((void**)&gene1, g_gene1);
    cudaGetSymbolAddress((void**)&xs, g_xs);
    cudaGetSymbolAddress((void**)&agg, g_agg);
    cudaGetSymbolAddress((void**)&mbuf, g_m);
    cudaGetSymbolAddress((void**)&den, g_den);
    cudaGetSymbolAddress((void**)&stats, g_stats);
    cudaGetSymbolAddress((void**)&w1sf, g_w1sf);
    cudaGetSymbolAddress((void**)&shW, g_shW);
    cudaGetSymbolAddress((void**)&wldc, g_wldc);

    float* out_gene = (float*)d_out;
    float* out_dis  = (float*)d_out + (size_t)NG * CH;

    const int T = 256;
    auto blocks = [](int n, int t) { return (n + t - 1) / t; };

    // -------- encoders (pre-BN activations) --------
    fill_kernel<<<2, T>>>(stats, 0.f, 4 * CH);
    sgemm_kernel<<<dim3(1, blocks(NG, 128)), 256>>>(x_gene, Wg, bg, hg, NG, CH, Fg, 1);
    sgemm_kernel<<<dim3(1, blocks(ND, 128)), 256>>>(x_dis,  Wd, bd, hd, ND, CH, Fd, 1);
    colstats_kernel<<<blocks(NG, 128), 128>>>(hg, NG, stats, stats + 128);
    colstats_kernel<<<blocks(ND, 128), 128>>>(hd, ND, stats + 256, stats + 384);
    bn_finalize_kernel<<<1, 256>>>(gg, betag, gd, betad);
    scaleW_kernel<<<2, 256>>>(W1s);   // fold disease BN into W1s

    // -------- GAT 1: dis -> gene --------
    fill_kernel<<<blocks(NG * 4, T), T>>>(mbuf, -INFINITY, NG * 4);
    fill_kernel<<<blocks(NG * 4, T), T>>>(den, 0.f, NG * 4);
    fill_kernel<<<blocks(NG * CH, T), T>>>(agg, 0.f, NG * CH);
    // xs = BN(hd) @ W1s = hd @ W1s' + shW
    sgemm_kernel<<<dim3(4, blocks(ND, 128)), 256>>>(hd, w1sf, shW, xs, ND, HC, CH, 2);
    ls_kernel<<<blocks(ND * 32, T), T>>>(a1s, ND);
    wld_kernel<<<blocks(512 * 32, T), T>>>(W1d, a1d, 1);  // scaled by gene BN
    ldc_kernel<<<1, 128>>>();
    ld_kernel<<<blocks(NG * 32, T), T>>>(hg, NG);         // ld = BN(hg)@wld folded
    {
        int nT = E1 + ND;
        edge_max_kernel<<<blocks(nT, T), T>>>(e1_src, e1_dst, E1, ND);
        edge_den_kernel<<<blocks(nT, T), T>>>(e1_src, e1_dst, E1, ND);
        edge_agg_kernel<<<blocks(nT * 32, T), T>>>(e1_src, e1_dst, E1, ND);
    }
    combine_affine_kernel<<<blocks(NG * CH, T), T>>>(hg, b1, gene1, NG * CH);

    // -------- GAT 2: gene -> gene --------
    fill_kernel<<<blocks(NG * 4, T), T>>>(mbuf, -INFINITY, NG * 4);
    fill_kernel<<<blocks(NG * 4, T), T>>>(den, 0.f, NG * 4);
    fill_kernel<<<blocks(NG * CH, T), T>>>(agg, 0.f, NG * CH);
    sgemm_kernel<<<dim3(4, blocks(NG, 128)), 256>>>(gene1, W2s, nullptr, xs, NG, HC, CH, 0);
    ls_kernel<<<blocks(NG * 32, T), T>>>(a2s, NG);
    wld_kernel<<<blocks(512 * 32, T), T>>>(W2d, a2d, 0);  // no BN fold
    fill_kernel<<<1, 32>>>(wldc, 0.f, 4);
    ld_kernel<<<blocks(NG * 32, T), T>>>(gene1, NG);
    {
        int nT = E2 + NG;
        edge_max_kernel<<<blocks(nT, T), T>>>(e2_src, e2_dst, E2, NG);
        edge_den_kernel<<<blocks(nT, T), T>>>(e2_src, e2_dst, E2, NG);
        edge_agg_kernel<<<blocks(nT * 32, T), T>>>(e2_src, e2_dst, E2, NG);
    }

    // -------- outputs: [gene | dis] --------
    combine_kernel<<<blocks(NG * CH, T), T>>>(gene1, b2, out_gene, NG * CH);
    copy_affine_kernel<<<blocks(ND * CH, T), T>>>(hd, out_dis, ND * CH);
}